// round 1
// baseline (speedup 1.0000x reference)
#include <cuda_runtime.h>
#include <math.h>

// ---------------------------------------------------------------------------
// Problem constants
// ---------------------------------------------------------------------------
#define BATCH 2
#define DD 8
#define CH 256
#define WW 84
#define HH 84
#define NUM_HEADS 8
#define HEAD_DIM 32
#define WIN_N 98           // 2*7*7
#define NWIN_PER_B 576     // 4*12*12
#define NWIN_TOT 1152      // BATCH * 576
#define T_TOKENS 112896    // BATCH*DD*HH*WW
#define HIDDEN 1024
#define QK_SCALE 0.17677669529663689f   // 32^-0.5

// ---------------------------------------------------------------------------
// Device scratch (static allocation; no cudaMalloc allowed)
// ---------------------------------------------------------------------------
__device__ float g_xt  [T_TOKENS * CH];     // transposed input, token-major (B,D,H,W,C)
__device__ float g_xw  [T_TOKENS * CH];     // LN1 + shift + window-partitioned
__device__ float g_q   [T_TOKENS * CH];     // (win, head, n, hd)
__device__ float g_k   [T_TOKENS * CH];
__device__ float g_v   [T_TOKENS * CH];
__device__ float g_attn[T_TOKENS * CH];     // attention output (win, n, C)
__device__ float g_xres[T_TOKENS * CH];     // residual after proj
__device__ float g_h2  [T_TOKENS * CH];     // LN2 output
__device__ float g_fc1 [T_TOKENS * HIDDEN]; // fc1+gelu output
__device__ float g_y   [T_TOKENS * CH];     // final token-major output

// ---------------------------------------------------------------------------
// Stage 0: transpose (B,D,C,W,H) -> token-major (B,D,H,W,C)
// ---------------------------------------------------------------------------
__global__ __launch_bounds__(256) void transpose_in_kernel(
    const float* __restrict__ x, float* __restrict__ xt)
{
    __shared__ float tile[32][33];
    int bdw = blockIdx.z;                 // 0..(16*84-1)
    int bd = bdw / WW, w = bdw % WW;
    int c0 = blockIdx.x * 32;
    int h0 = blockIdx.y * 32;
    int tx = threadIdx.x;

    #pragma unroll
    for (int cc = threadIdx.y; cc < 32; cc += 8) {
        int h = h0 + tx;
        if (h < HH)
            tile[cc][tx] = x[(size_t)(bd * CH + c0 + cc) * (WW * HH) + w * HH + h];
    }
    __syncthreads();
    #pragma unroll
    for (int hh = threadIdx.y; hh < 32; hh += 8) {
        int h = h0 + hh;
        if (h < HH)
            xt[(size_t)(bd * (HH * WW) + h * WW + w) * CH + c0 + tx] = tile[tx][hh];
    }
}

// ---------------------------------------------------------------------------
// Stage final: transpose token-major y -> (B,D,C,W,H) output
// ---------------------------------------------------------------------------
__global__ __launch_bounds__(256) void transpose_out_kernel(
    const float* __restrict__ y, float* __restrict__ out)
{
    __shared__ float tile[32][33];
    int bdw = blockIdx.z;
    int bd = bdw / WW, w = bdw % WW;
    int c0 = blockIdx.x * 32;
    int h0 = blockIdx.y * 32;
    int tx = threadIdx.x;

    #pragma unroll
    for (int hh = threadIdx.y; hh < 32; hh += 8) {
        int h = h0 + hh;
        if (h < HH)
            tile[hh][tx] = y[(size_t)(bd * (HH * WW) + h * WW + w) * CH + c0 + tx];
    }
    __syncthreads();
    #pragma unroll
    for (int cc = threadIdx.y; cc < 32; cc += 8) {
        int h = h0 + tx;
        if (h < HH)
            out[(size_t)(bd * CH + c0 + cc) * (WW * HH) + w * HH + h] = tile[tx][cc];
    }
}

// ---------------------------------------------------------------------------
// LayerNorm over C=256 per token. SCATTER=true also applies cyclic shift and
// window partition (LN1 path); SCATTER=false writes in place order (LN2 path).
// ---------------------------------------------------------------------------
template <bool SCATTER>
__global__ __launch_bounds__(256) void ln_kernel(
    const float* __restrict__ in, const float* __restrict__ gamma,
    const float* __restrict__ beta, float* __restrict__ out)
{
    int t = blockIdx.x;
    int tid = threadIdx.x;
    float v = in[(size_t)t * CH + tid];

    // block reduction of sum and sumsq
    float s1 = v, s2 = v * v;
    #pragma unroll
    for (int o = 16; o > 0; o >>= 1) {
        s1 += __shfl_xor_sync(0xffffffffu, s1, o);
        s2 += __shfl_xor_sync(0xffffffffu, s2, o);
    }
    __shared__ float ws1[8], ws2[8];
    __shared__ float s_mean, s_rstd;
    int lane = tid & 31, wid = tid >> 5;
    if (lane == 0) { ws1[wid] = s1; ws2[wid] = s2; }
    __syncthreads();
    if (wid == 0) {
        float a = (lane < 8) ? ws1[lane] : 0.f;
        float b = (lane < 8) ? ws2[lane] : 0.f;
        #pragma unroll
        for (int o = 4; o > 0; o >>= 1) {
            a += __shfl_xor_sync(0xffffffffu, a, o);
            b += __shfl_xor_sync(0xffffffffu, b, o);
        }
        if (lane == 0) {
            float mean = a * (1.0f / CH);
            float var = b * (1.0f / CH) - mean * mean;
            s_mean = mean;
            s_rstd = rsqrtf(var + 1e-5f);
        }
    }
    __syncthreads();
    float yv = (v - s_mean) * s_rstd * gamma[tid] + beta[tid];

    size_t row;
    if (SCATTER) {
        int bd = t / (HH * WW);
        int hw = t % (HH * WW);
        int h = hw / WW, w = hw % WW;
        int b = bd / DD, d = bd % DD;
        int dp = (d + DD - 1) % DD;     // roll shift -1
        int hp = (h + HH - 3) % HH;     // roll shift -3
        int wp = (w + WW - 3) % WW;
        int i = dp >> 1, pd = dp & 1;
        int j = hp / 7, ph = hp % 7;
        int kk = wp / 7, pw = wp % 7;
        int win = ((b * 4 + i) * 12 + j) * 12 + kk;
        int nn = pd * 49 + ph * 7 + pw;
        row = (size_t)win * WIN_N + nn;
    } else {
        row = (size_t)t;
    }
    out[row * CH + tid] = yv;
}

// ---------------------------------------------------------------------------
// Register-blocked SGEMM: out[m,n] = sum_k A[m,k] * B[n,k]  (A: MxK, B: NxK,
// both row-major). 128x128 block tile, BK=8, 8x8 per-thread microtile,
// 256 threads. M,N multiples of 128; K multiple of 8. Epilogue is a functor.
// ---------------------------------------------------------------------------
template <class Epi>
__global__ __launch_bounds__(256) void gemm_nt_kernel(
    const float* __restrict__ A, const float* __restrict__ Bm, int K, Epi epi)
{
    __shared__ float As[8][128];
    __shared__ float Bs[8][128];
    int tid = threadIdx.x;
    int tx = tid & 15, ty = tid >> 4;
    const float* Ablk = A + (size_t)blockIdx.y * 128 * K;
    const float* Bblk = Bm + (size_t)blockIdx.x * 128 * K;
    int lr = tid >> 1;            // 0..127
    int lc = (tid & 1) * 4;       // 0 or 4

    float acc[8][8];
    #pragma unroll
    for (int i = 0; i < 8; i++)
        #pragma unroll
        for (int j = 0; j < 8; j++) acc[i][j] = 0.f;

    for (int kt = 0; kt < K; kt += 8) {
        float4 a4 = *(const float4*)(Ablk + (size_t)lr * K + kt + lc);
        float4 b4 = *(const float4*)(Bblk + (size_t)lr * K + kt + lc);
        As[lc + 0][lr] = a4.x; As[lc + 1][lr] = a4.y;
        As[lc + 2][lr] = a4.z; As[lc + 3][lr] = a4.w;
        Bs[lc + 0][lr] = b4.x; Bs[lc + 1][lr] = b4.y;
        Bs[lc + 2][lr] = b4.z; Bs[lc + 3][lr] = b4.w;
        __syncthreads();
        #pragma unroll
        for (int k = 0; k < 8; k++) {
            float ra[8], rb[8];
            *(float4*)(ra)     = *(const float4*)&As[k][ty * 8];
            *(float4*)(ra + 4) = *(const float4*)&As[k][ty * 8 + 4];
            *(float4*)(rb)     = *(const float4*)&Bs[k][tx * 8];
            *(float4*)(rb + 4) = *(const float4*)&Bs[k][tx * 8 + 4];
            #pragma unroll
            for (int i = 0; i < 8; i++)
                #pragma unroll
                for (int j = 0; j < 8; j++)
                    acc[i][j] = fmaf(ra[i], rb[j], acc[i][j]);
        }
        __syncthreads();
    }

    int m0 = blockIdx.y * 128 + ty * 8;
    int n0 = blockIdx.x * 128 + tx * 8;
    #pragma unroll
    for (int i = 0; i < 8; i++)
        #pragma unroll
        for (int j = 0; j < 8; j++)
            epi(m0 + i, n0 + j, acc[i][j]);
}

// ---- Epilogues --------------------------------------------------------------

struct EpiQKV {
    float* q; float* k; float* v;
    __device__ __forceinline__ void operator()(int m, int n, float val) const {
        int win = m / WIN_N, nn = m % WIN_N;
        int which = n >> 8;          // 0=q 1=k 2=v
        int c = n & 255;
        int head = c >> 5, dd = c & 31;
        size_t idx = ((size_t)(win * NUM_HEADS + head) * WIN_N + nn) * HEAD_DIM + dd;
        if (which == 0)      q[idx] = val * QK_SCALE;
        else if (which == 1) k[idx] = val;
        else                 v[idx] = val;
    }
};

struct EpiProj {
    const float* bias; const float* xt; float* xres;
    __device__ __forceinline__ void operator()(int m, int n, float val) const {
        int win = m / WIN_N, nn = m % WIN_N;
        int b = win / NWIN_PER_B, iw = win % NWIN_PER_B;
        int i = iw / 144, j = (iw / 12) % 12, kk = iw % 12;
        int pd = nn / 49, ph = (nn / 7) % 7, pw = nn % 7;
        int d = (i * 2 + pd + 1) & 7;        // roll shift +1
        int h = (j * 7 + ph + 3) % HH;       // roll shift +3
        int w = (kk * 7 + pw + 3) % WW;
        size_t t = ((size_t)(b * DD + d) * HH + h) * WW + w;
        xres[t * CH + n] = xt[t * CH + n] + val + bias[n];
    }
};

struct EpiFC1 {
    const float* bias; float* out;
    __device__ __forceinline__ void operator()(int m, int n, float val) const {
        float x = val + bias[n];
        // exact GELU: 0.5*x*(1+erf(x/sqrt(2)))
        out[(size_t)m * HIDDEN + n] = 0.5f * x * (1.0f + erff(x * 0.7071067811865476f));
    }
};

struct EpiFC2 {
    const float* bias; const float* xres; float* y;
    __device__ __forceinline__ void operator()(int m, int n, float val) const {
        y[(size_t)m * CH + n] = xres[(size_t)m * CH + n] + val + bias[n];
    }
};

// ---------------------------------------------------------------------------
// Window attention: one block per (window, head). Q pre-scaled.
// Relative position bias index and shift mask computed on the fly.
// ---------------------------------------------------------------------------
#define SMEM_ATTN (((3 * 3136 + 9604) * 4) + 98 * 4)

__global__ __launch_bounds__(256) void attn_kernel(
    const float* __restrict__ q, const float* __restrict__ k,
    const float* __restrict__ v, const float* __restrict__ rpb,
    float* __restrict__ attn_out)
{
    extern __shared__ float smem[];
    float* sQ = smem;
    float* sK = sQ + 3136;
    float* sV = sK + 3136;
    float* sS = sV + 3136;
    int* cls = (int*)(sS + 9604);

    int tid = threadIdx.x;
    int win = blockIdx.x >> 3;       // /8
    int head = blockIdx.x & 7;
    size_t base = ((size_t)(win * NUM_HEADS + head) * WIN_N) * HEAD_DIM;

    for (int i = tid; i < 3136; i += 256) {
        sQ[i] = q[base + i];
        sK[i] = k[base + i];
        sV[i] = v[base + i];
    }
    if (tid < WIN_N) {
        int iw = win % NWIN_PER_B;
        int i = iw / 144, j = (iw / 12) % 12, kk = iw % 12;
        int pd = tid / 49, ph = (tid / 7) % 7, pw = tid % 7;
        int d = i * 2 + pd, h = j * 7 + ph, w = kk * 7 + pw;
        int ld = (d < 6) ? 0 : ((d < 7) ? 1 : 2);
        int lh = (h < 77) ? 0 : ((h < 81) ? 1 : 2);
        int lw = (w < 77) ? 0 : ((w < 81) ? 1 : 2);
        cls[tid] = ld * 9 + lh * 3 + lw;
    }
    __syncthreads();

    // scores S = Q K^T + bias + mask
    for (int idx = tid; idx < WIN_N * WIN_N; idx += 256) {
        int n = idx / WIN_N, m = idx % WIN_N;
        const float* qr = sQ + n * 32;
        const float* kr = sK + m * 32;
        float dot = 0.f;
        #pragma unroll
        for (int d = 0; d < 32; d++) dot = fmaf(qr[d], kr[d], dot);
        int dn = n / 49, hn = (n / 7) % 7, wn = n % 7;
        int dm = m / 49, hm = (m / 7) % 7, wm = m % 7;
        int ridx = ((dn - dm + 1) * 13 + (hn - hm + 6)) * 13 + (wn - wm + 6);
        float bias = rpb[ridx * NUM_HEADS + head];
        float maskv = (cls[n] != cls[m]) ? -100.0f : 0.0f;
        sS[idx] = dot + bias + maskv;
    }
    __syncthreads();

    // softmax per row (warp per row, 8 warps round-robin over 98 rows)
    int lane = tid & 31, wid = tid >> 5;
    for (int r = wid; r < WIN_N; r += 8) {
        float* row = sS + r * WIN_N;
        float mx = -1e30f;
        for (int m = lane; m < WIN_N; m += 32) mx = fmaxf(mx, row[m]);
        #pragma unroll
        for (int o = 16; o > 0; o >>= 1) mx = fmaxf(mx, __shfl_xor_sync(0xffffffffu, mx, o));
        float sum = 0.f;
        for (int m = lane; m < WIN_N; m += 32) {
            float e = __expf(row[m] - mx);
            row[m] = e;
            sum += e;
        }
        #pragma unroll
        for (int o = 16; o > 0; o >>= 1) sum += __shfl_xor_sync(0xffffffffu, sum, o);
        float inv = 1.0f / sum;
        for (int m = lane; m < WIN_N; m += 32) row[m] *= inv;
    }
    __syncthreads();

    // O = P V ; write (win, n, head*32+dd)
    for (int idx = tid; idx < WIN_N * HEAD_DIM; idx += 256) {
        int n = idx / HEAD_DIM, dd = idx % HEAD_DIM;
        const float* prow = sS + n * WIN_N;
        float sum = 0.f;
        for (int m = 0; m < WIN_N; m++) sum = fmaf(prow[m], sV[m * 32 + dd], sum);
        attn_out[((size_t)win * WIN_N + n) * CH + head * 32 + dd] = sum;
    }
}

// ---------------------------------------------------------------------------
// Host launcher
// ---------------------------------------------------------------------------
extern "C" void kernel_launch(void* const* d_in, const int* in_sizes, int n_in,
                              void* d_out, int out_size)
{
    const float* x      = (const float*)d_in[0];
    const float* n1g    = (const float*)d_in[1];
    const float* n1b    = (const float*)d_in[2];
    const float* qkv_w  = (const float*)d_in[3];
    const float* rpb    = (const float*)d_in[4];
    const float* proj_w = (const float*)d_in[5];
    const float* proj_b = (const float*)d_in[6];
    const float* n2g    = (const float*)d_in[7];
    const float* n2b    = (const float*)d_in[8];
    const float* fc1_w  = (const float*)d_in[9];
    const float* fc1_b  = (const float*)d_in[10];
    const float* fc2_w  = (const float*)d_in[11];
    const float* fc2_b  = (const float*)d_in[12];
    float* out = (float*)d_out;

    float *xt, *xw, *q, *k, *v, *attn, *xres, *h2, *fc1o, *y;
    cudaGetSymbolAddress((void**)&xt,   g_xt);
    cudaGetSymbolAddress((void**)&xw,   g_xw);
    cudaGetSymbolAddress((void**)&q,    g_q);
    cudaGetSymbolAddress((void**)&k,    g_k);
    cudaGetSymbolAddress((void**)&v,    g_v);
    cudaGetSymbolAddress((void**)&attn, g_attn);
    cudaGetSymbolAddress((void**)&xres, g_xres);
    cudaGetSymbolAddress((void**)&h2,   g_h2);
    cudaGetSymbolAddress((void**)&fc1o, g_fc1);
    cudaGetSymbolAddress((void**)&y,    g_y);

    cudaFuncSetAttribute(attn_kernel, cudaFuncAttributeMaxDynamicSharedMemorySize,
                         SMEM_ATTN);

    dim3 tb(32, 8);
    dim3 tgrid(CH / 32, 3, BATCH * DD * WW);  // (8, 3, 1344)

    // Stage 0: transpose input to token-major
    transpose_in_kernel<<<tgrid, tb>>>(x, xt);

    // Stage 1: LN1 + shift + window partition
    ln_kernel<true><<<T_TOKENS, 256>>>(xt, n1g, n1b, xw);

    // Stage 2: QKV GEMM (112896 x 256) @ (768 x 256)^T, split into q/k/v
    {
        EpiQKV e{q, k, v};
        gemm_nt_kernel<EpiQKV><<<dim3(768 / 128, T_TOKENS / 128), 256>>>(xw, qkv_w, CH, e);
    }

    // Stage 3: window attention
    attn_kernel<<<NWIN_TOT * NUM_HEADS, 256, SMEM_ATTN>>>(q, k, v, rpb, attn);

    // Stage 4: proj GEMM + bias + window reverse + shift back + residual
    {
        EpiProj e{proj_b, xt, xres};
        gemm_nt_kernel<EpiProj><<<dim3(CH / 128, T_TOKENS / 128), 256>>>(attn, proj_w, CH, e);
    }

    // Stage 5: LN2
    ln_kernel<false><<<T_TOKENS, 256>>>(xres, n2g, n2b, h2);

    // Stage 6: fc1 GEMM + bias + exact GELU
    {
        EpiFC1 e{fc1_b, fc1o};
        gemm_nt_kernel<EpiFC1><<<dim3(HIDDEN / 128, T_TOKENS / 128), 256>>>(h2, fc1_w, CH, e);
    }

    // Stage 7: fc2 GEMM + bias + residual
    {
        EpiFC2 e{fc2_b, xres, y};
        gemm_nt_kernel<EpiFC2><<<dim3(CH / 128, T_TOKENS / 128), 256>>>(fc1o, fc2_w, HIDDEN, e);
    }

    // Stage 8: transpose back to (B,D,C,W,H)
    transpose_out_kernel<<<tgrid, tb>>>(y, out);
}

// round 2
// speedup vs baseline: 1.4274x; 1.4274x over previous
#include <cuda_runtime.h>
#include <math.h>
#include <stdint.h>

// ---------------------------------------------------------------------------
// Problem constants
// ---------------------------------------------------------------------------
#define BATCH 2
#define DD 8
#define CH 256
#define WW 84
#define HH 84
#define NUM_HEADS 8
#define HEAD_DIM 32
#define WIN_N 98           // 2*7*7
#define NWIN_PER_B 576     // 4*12*12
#define NWIN_TOT 1152      // BATCH * 576
#define T_TOKENS 112896    // BATCH*DD*HH*WW
#define HIDDEN 1024
#define QK_SCALE 0.17677669529663689f   // 32^-0.5

// ---------------------------------------------------------------------------
// Device scratch (static allocation; no cudaMalloc allowed)
// ---------------------------------------------------------------------------
__device__ float g_xt  [T_TOKENS * CH];     // transposed input, token-major (B,D,H,W,C)
__device__ float g_xw  [T_TOKENS * CH];     // LN1 + shift + window-partitioned
__device__ float g_q   [T_TOKENS * CH];     // (win, head, n, hd)
__device__ float g_k   [T_TOKENS * CH];
__device__ float g_v   [T_TOKENS * CH];
__device__ float g_attn[T_TOKENS * CH];     // attention output (win, n, C)
__device__ float g_xres[T_TOKENS * CH];     // residual after proj
__device__ float g_h2  [T_TOKENS * CH];     // LN2 output
__device__ float g_fc1 [T_TOKENS * HIDDEN]; // fc1+gelu output
__device__ float g_y   [T_TOKENS * CH];     // final token-major output

// ---------------------------------------------------------------------------
// tf32 helpers
// ---------------------------------------------------------------------------
__device__ __forceinline__ uint32_t f2tf32(float x) {
    uint32_t r;
    asm("cvt.rna.tf32.f32 %0, %1;" : "=r"(r) : "f"(x));
    return r;
}

__device__ __forceinline__ void mma_tf32(float* c, const uint32_t* a, const uint32_t* b) {
    asm volatile(
        "mma.sync.aligned.m16n8k8.row.col.f32.tf32.tf32.f32 "
        "{%0,%1,%2,%3}, {%4,%5,%6,%7}, {%8,%9}, {%0,%1,%2,%3};\n"
        : "+f"(c[0]), "+f"(c[1]), "+f"(c[2]), "+f"(c[3])
        : "r"(a[0]), "r"(a[1]), "r"(a[2]), "r"(a[3]), "r"(b[0]), "r"(b[1]));
}

// ---------------------------------------------------------------------------
// Stage 0: transpose (B,D,C,W,H) -> token-major (B,D,H,W,C)
// ---------------------------------------------------------------------------
__global__ __launch_bounds__(256) void transpose_in_kernel(
    const float* __restrict__ x, float* __restrict__ xt)
{
    __shared__ float tile[32][33];
    int bdw = blockIdx.z;                 // 0..(16*84-1)
    int bd = bdw / WW, w = bdw % WW;
    int c0 = blockIdx.x * 32;
    int h0 = blockIdx.y * 32;
    int tx = threadIdx.x;

    #pragma unroll
    for (int cc = threadIdx.y; cc < 32; cc += 8) {
        int h = h0 + tx;
        if (h < HH)
            tile[cc][tx] = x[(size_t)(bd * CH + c0 + cc) * (WW * HH) + w * HH + h];
    }
    __syncthreads();
    #pragma unroll
    for (int hh = threadIdx.y; hh < 32; hh += 8) {
        int h = h0 + hh;
        if (h < HH)
            xt[(size_t)(bd * (HH * WW) + h * WW + w) * CH + c0 + tx] = tile[tx][hh];
    }
}

// ---------------------------------------------------------------------------
// Stage final: transpose token-major y -> (B,D,C,W,H) output
// ---------------------------------------------------------------------------
__global__ __launch_bounds__(256) void transpose_out_kernel(
    const float* __restrict__ y, float* __restrict__ out)
{
    __shared__ float tile[32][33];
    int bdw = blockIdx.z;
    int bd = bdw / WW, w = bdw % WW;
    int c0 = blockIdx.x * 32;
    int h0 = blockIdx.y * 32;
    int tx = threadIdx.x;

    #pragma unroll
    for (int hh = threadIdx.y; hh < 32; hh += 8) {
        int h = h0 + hh;
        if (h < HH)
            tile[hh][tx] = y[(size_t)(bd * (HH * WW) + h * WW + w) * CH + c0 + tx];
    }
    __syncthreads();
    #pragma unroll
    for (int cc = threadIdx.y; cc < 32; cc += 8) {
        int h = h0 + tx;
        if (h < HH)
            out[(size_t)(bd * CH + c0 + cc) * (WW * HH) + w * HH + h] = tile[tx][cc];
    }
}

// ---------------------------------------------------------------------------
// LayerNorm over C=256 per token. SCATTER=true also applies cyclic shift and
// window partition (LN1 path); SCATTER=false writes in place order (LN2 path).
// ---------------------------------------------------------------------------
template <bool SCATTER>
__global__ __launch_bounds__(256) void ln_kernel(
    const float* __restrict__ in, const float* __restrict__ gamma,
    const float* __restrict__ beta, float* __restrict__ out)
{
    int t = blockIdx.x;
    int tid = threadIdx.x;
    float v = in[(size_t)t * CH + tid];

    float s1 = v, s2 = v * v;
    #pragma unroll
    for (int o = 16; o > 0; o >>= 1) {
        s1 += __shfl_xor_sync(0xffffffffu, s1, o);
        s2 += __shfl_xor_sync(0xffffffffu, s2, o);
    }
    __shared__ float ws1[8], ws2[8];
    __shared__ float s_mean, s_rstd;
    int lane = tid & 31, wid = tid >> 5;
    if (lane == 0) { ws1[wid] = s1; ws2[wid] = s2; }
    __syncthreads();
    if (wid == 0) {
        float a = (lane < 8) ? ws1[lane] : 0.f;
        float b = (lane < 8) ? ws2[lane] : 0.f;
        #pragma unroll
        for (int o = 4; o > 0; o >>= 1) {
            a += __shfl_xor_sync(0xffffffffu, a, o);
            b += __shfl_xor_sync(0xffffffffu, b, o);
        }
        if (lane == 0) {
            float mean = a * (1.0f / CH);
            float var = b * (1.0f / CH) - mean * mean;
            s_mean = mean;
            s_rstd = rsqrtf(var + 1e-5f);
        }
    }
    __syncthreads();
    float yv = (v - s_mean) * s_rstd * gamma[tid] + beta[tid];

    size_t row;
    if (SCATTER) {
        int bd = t / (HH * WW);
        int hw = t % (HH * WW);
        int h = hw / WW, w = hw % WW;
        int b = bd / DD, d = bd % DD;
        int dp = (d + DD - 1) % DD;     // roll shift -1
        int hp = (h + HH - 3) % HH;     // roll shift -3
        int wp = (w + WW - 3) % WW;
        int i = dp >> 1, pd = dp & 1;
        int j = hp / 7, ph = hp % 7;
        int kk = wp / 7, pw = wp % 7;
        int win = ((b * 4 + i) * 12 + j) * 12 + kk;
        int nn = pd * 49 + ph * 7 + pw;
        row = (size_t)win * WIN_N + nn;
    } else {
        row = (size_t)t;
    }
    out[row * CH + tid] = yv;
}

// ---------------------------------------------------------------------------
// TF32 tensor-core GEMM: out[m,n] = sum_k A[m,k] * B[n,k]  (A: MxK, B: NxK,
// row-major). Block tile 128x128, BK=16, 8 warps (4x2), warp tile 32x64,
// mma.m16n8k8.tf32. M,N multiples of 128; K multiple of 16.
// Smem [row][k] with row stride 20 words -> conflict-free fragment loads.
// ---------------------------------------------------------------------------
template <class Epi>
__global__ __launch_bounds__(256) void gemm_tf32_kernel(
    const float* __restrict__ A, const float* __restrict__ Bm, int K, Epi epi)
{
    __shared__ uint32_t As[128][20];
    __shared__ uint32_t Bs[128][20];

    int tid = threadIdx.x;
    int warp = tid >> 5, lane = tid & 31;
    int wm = (warp >> 1) * 32;      // warp m offset in tile
    int wn = (warp & 1) * 64;       // warp n offset in tile
    int g = lane >> 2, t4 = lane & 3;

    const float* Ab = A + (size_t)blockIdx.y * 128 * K;
    const float* Bb = Bm + (size_t)blockIdx.x * 128 * K;

    float acc[2][8][4];
    #pragma unroll
    for (int mi = 0; mi < 2; mi++)
        #pragma unroll
        for (int ni = 0; ni < 8; ni++)
            #pragma unroll
            for (int e = 0; e < 4; e++) acc[mi][ni][e] = 0.f;

    int ldr = tid >> 1;                 // row 0..127 (pairs of threads per row)
    int ldk = (tid & 1) * 8;            // k offset 0 or 8

    for (int kt = 0; kt < K; kt += 16) {
        // Stage A and B tiles (convert to tf32 once here)
        float4 a0 = *(const float4*)(Ab + (size_t)ldr * K + kt + ldk);
        float4 a1 = *(const float4*)(Ab + (size_t)ldr * K + kt + ldk + 4);
        float4 b0 = *(const float4*)(Bb + (size_t)ldr * K + kt + ldk);
        float4 b1 = *(const float4*)(Bb + (size_t)ldr * K + kt + ldk + 4);
        As[ldr][ldk + 0] = f2tf32(a0.x); As[ldr][ldk + 1] = f2tf32(a0.y);
        As[ldr][ldk + 2] = f2tf32(a0.z); As[ldr][ldk + 3] = f2tf32(a0.w);
        As[ldr][ldk + 4] = f2tf32(a1.x); As[ldr][ldk + 5] = f2tf32(a1.y);
        As[ldr][ldk + 6] = f2tf32(a1.z); As[ldr][ldk + 7] = f2tf32(a1.w);
        Bs[ldr][ldk + 0] = f2tf32(b0.x); Bs[ldr][ldk + 1] = f2tf32(b0.y);
        Bs[ldr][ldk + 2] = f2tf32(b0.z); Bs[ldr][ldk + 3] = f2tf32(b0.w);
        Bs[ldr][ldk + 4] = f2tf32(b1.x); Bs[ldr][ldk + 5] = f2tf32(b1.y);
        Bs[ldr][ldk + 6] = f2tf32(b1.z); Bs[ldr][ldk + 7] = f2tf32(b1.w);
        __syncthreads();

        #pragma unroll
        for (int ks = 0; ks < 16; ks += 8) {
            uint32_t afr[2][4], bfr[8][2];
            #pragma unroll
            for (int mi = 0; mi < 2; mi++) {
                int r = wm + mi * 16;
                afr[mi][0] = As[r + g][ks + t4];
                afr[mi][1] = As[r + g + 8][ks + t4];
                afr[mi][2] = As[r + g][ks + t4 + 4];
                afr[mi][3] = As[r + g + 8][ks + t4 + 4];
            }
            #pragma unroll
            for (int ni = 0; ni < 8; ni++) {
                int r = wn + ni * 8;
                bfr[ni][0] = Bs[r + g][ks + t4];
                bfr[ni][1] = Bs[r + g][ks + t4 + 4];
            }
            #pragma unroll
            for (int mi = 0; mi < 2; mi++)
                #pragma unroll
                for (int ni = 0; ni < 8; ni++)
                    mma_tf32(acc[mi][ni], afr[mi], bfr[ni]);
        }
        __syncthreads();
    }

    int m0 = blockIdx.y * 128 + wm;
    int n0 = blockIdx.x * 128 + wn;
    #pragma unroll
    for (int mi = 0; mi < 2; mi++) {
        #pragma unroll
        for (int ni = 0; ni < 8; ni++) {
            int mr = m0 + mi * 16 + g;
            int nc = n0 + ni * 8 + t4 * 2;
            epi(mr,     nc,     acc[mi][ni][0]);
            epi(mr,     nc + 1, acc[mi][ni][1]);
            epi(mr + 8, nc,     acc[mi][ni][2]);
            epi(mr + 8, nc + 1, acc[mi][ni][3]);
        }
    }
}

// ---- Epilogues --------------------------------------------------------------

struct EpiQKV {
    float* q; float* k; float* v;
    __device__ __forceinline__ void operator()(int m, int n, float val) const {
        int win = m / WIN_N, nn = m % WIN_N;
        int which = n >> 8;          // 0=q 1=k 2=v
        int c = n & 255;
        int head = c >> 5, dd = c & 31;
        size_t idx = ((size_t)(win * NUM_HEADS + head) * WIN_N + nn) * HEAD_DIM + dd;
        if (which == 0)      q[idx] = val * QK_SCALE;
        else if (which == 1) k[idx] = val;
        else                 v[idx] = val;
    }
};

struct EpiProj {
    const float* bias; const float* xt; float* xres;
    __device__ __forceinline__ void operator()(int m, int n, float val) const {
        int win = m / WIN_N, nn = m % WIN_N;
        int b = win / NWIN_PER_B, iw = win % NWIN_PER_B;
        int i = iw / 144, j = (iw / 12) % 12, kk = iw % 12;
        int pd = nn / 49, ph = (nn / 7) % 7, pw = nn % 7;
        int d = (i * 2 + pd + 1) & 7;        // roll shift +1
        int h = (j * 7 + ph + 3) % HH;       // roll shift +3
        int w = (kk * 7 + pw + 3) % WW;
        size_t t = ((size_t)(b * DD + d) * HH + h) * WW + w;
        xres[t * CH + n] = xt[t * CH + n] + val + bias[n];
    }
};

struct EpiFC1 {
    const float* bias; float* out;
    __device__ __forceinline__ void operator()(int m, int n, float val) const {
        float x = val + bias[n];
        out[(size_t)m * HIDDEN + n] = 0.5f * x * (1.0f + erff(x * 0.7071067811865476f));
    }
};

struct EpiFC2 {
    const float* bias; const float* xres; float* y;
    __device__ __forceinline__ void operator()(int m, int n, float val) const {
        y[(size_t)m * CH + n] = xres[(size_t)m * CH + n] + val + bias[n];
    }
};

// ---------------------------------------------------------------------------
// Window attention: one block per (window, head). Q pre-scaled.
// ---------------------------------------------------------------------------
#define SMEM_ATTN (((3 * 3136 + 9604) * 4) + 98 * 4)

__global__ __launch_bounds__(256) void attn_kernel(
    const float* __restrict__ q, const float* __restrict__ k,
    const float* __restrict__ v, const float* __restrict__ rpb,
    float* __restrict__ attn_out)
{
    extern __shared__ float smem[];
    float* sQ = smem;
    float* sK = sQ + 3136;
    float* sV = sK + 3136;
    float* sS = sV + 3136;
    int* cls = (int*)(sS + 9604);

    int tid = threadIdx.x;
    int win = blockIdx.x >> 3;
    int head = blockIdx.x & 7;
    size_t base = ((size_t)(win * NUM_HEADS + head) * WIN_N) * HEAD_DIM;

    for (int i = tid; i < 3136; i += 256) {
        sQ[i] = q[base + i];
        sK[i] = k[base + i];
        sV[i] = v[base + i];
    }
    if (tid < WIN_N) {
        int iw = win % NWIN_PER_B;
        int i = iw / 144, j = (iw / 12) % 12, kk = iw % 12;
        int pd = tid / 49, ph = (tid / 7) % 7, pw = tid % 7;
        int d = i * 2 + pd, h = j * 7 + ph, w = kk * 7 + pw;
        int ld = (d < 6) ? 0 : ((d < 7) ? 1 : 2);
        int lh = (h < 77) ? 0 : ((h < 81) ? 1 : 2);
        int lw = (w < 77) ? 0 : ((w < 81) ? 1 : 2);
        cls[tid] = ld * 9 + lh * 3 + lw;
    }
    __syncthreads();

    for (int idx = tid; idx < WIN_N * WIN_N; idx += 256) {
        int n = idx / WIN_N, m = idx % WIN_N;
        const float* qr = sQ + n * 32;
        const float* kr = sK + m * 32;
        float dot = 0.f;
        #pragma unroll
        for (int d = 0; d < 32; d++) dot = fmaf(qr[d], kr[d], dot);
        int dn = n / 49, hn = (n / 7) % 7, wn = n % 7;
        int dm = m / 49, hm = (m / 7) % 7, wm = m % 7;
        int ridx = ((dn - dm + 1) * 13 + (hn - hm + 6)) * 13 + (wn - wm + 6);
        float bias = rpb[ridx * NUM_HEADS + head];
        float maskv = (cls[n] != cls[m]) ? -100.0f : 0.0f;
        sS[idx] = dot + bias + maskv;
    }
    __syncthreads();

    int lane = tid & 31, wid = tid >> 5;
    for (int r = wid; r < WIN_N; r += 8) {
        float* row = sS + r * WIN_N;
        float mx = -1e30f;
        for (int m = lane; m < WIN_N; m += 32) mx = fmaxf(mx, row[m]);
        #pragma unroll
        for (int o = 16; o > 0; o >>= 1) mx = fmaxf(mx, __shfl_xor_sync(0xffffffffu, mx, o));
        float sum = 0.f;
        for (int m = lane; m < WIN_N; m += 32) {
            float e = __expf(row[m] - mx);
            row[m] = e;
            sum += e;
        }
        #pragma unroll
        for (int o = 16; o > 0; o >>= 1) sum += __shfl_xor_sync(0xffffffffu, sum, o);
        float inv = 1.0f / sum;
        for (int m = lane; m < WIN_N; m += 32) row[m] *= inv;
    }
    __syncthreads();

    for (int idx = tid; idx < WIN_N * HEAD_DIM; idx += 256) {
        int n = idx / HEAD_DIM, dd = idx % HEAD_DIM;
        const float* prow = sS + n * WIN_N;
        float sum = 0.f;
        for (int m = 0; m < WIN_N; m++) sum = fmaf(prow[m], sV[m * 32 + dd], sum);
        attn_out[((size_t)win * WIN_N + n) * CH + head * 32 + dd] = sum;
    }
}

// ---------------------------------------------------------------------------
// Host launcher
// ---------------------------------------------------------------------------
extern "C" void kernel_launch(void* const* d_in, const int* in_sizes, int n_in,
                              void* d_out, int out_size)
{
    const float* x      = (const float*)d_in[0];
    const float* n1g    = (const float*)d_in[1];
    const float* n1b    = (const float*)d_in[2];
    const float* qkv_w  = (const float*)d_in[3];
    const float* rpb    = (const float*)d_in[4];
    const float* proj_w = (const float*)d_in[5];
    const float* proj_b = (const float*)d_in[6];
    const float* n2g    = (const float*)d_in[7];
    const float* n2b    = (const float*)d_in[8];
    const float* fc1_w  = (const float*)d_in[9];
    const float* fc1_b  = (const float*)d_in[10];
    const float* fc2_w  = (const float*)d_in[11];
    const float* fc2_b  = (const float*)d_in[12];
    float* out = (float*)d_out;

    float *xt, *xw, *q, *k, *v, *attn, *xres, *h2, *fc1o, *y;
    cudaGetSymbolAddress((void**)&xt,   g_xt);
    cudaGetSymbolAddress((void**)&xw,   g_xw);
    cudaGetSymbolAddress((void**)&q,    g_q);
    cudaGetSymbolAddress((void**)&k,    g_k);
    cudaGetSymbolAddress((void**)&v,    g_v);
    cudaGetSymbolAddress((void**)&attn, g_attn);
    cudaGetSymbolAddress((void**)&xres, g_xres);
    cudaGetSymbolAddress((void**)&h2,   g_h2);
    cudaGetSymbolAddress((void**)&fc1o, g_fc1);
    cudaGetSymbolAddress((void**)&y,    g_y);

    cudaFuncSetAttribute(attn_kernel, cudaFuncAttributeMaxDynamicSharedMemorySize,
                         SMEM_ATTN);

    dim3 tb(32, 8);
    dim3 tgrid(CH / 32, 3, BATCH * DD * WW);

    transpose_in_kernel<<<tgrid, tb>>>(x, xt);
    ln_kernel<true><<<T_TOKENS, 256>>>(xt, n1g, n1b, xw);

    {
        EpiQKV e{q, k, v};
        gemm_tf32_kernel<EpiQKV><<<dim3(768 / 128, T_TOKENS / 128), 256>>>(xw, qkv_w, CH, e);
    }

    attn_kernel<<<NWIN_TOT * NUM_HEADS, 256, SMEM_ATTN>>>(q, k, v, rpb, attn);

    {
        EpiProj e{proj_b, xt, xres};
        gemm_tf32_kernel<EpiProj><<<dim3(CH / 128, T_TOKENS / 128), 256>>>(attn, proj_w, CH, e);
    }

    ln_kernel<false><<<T_TOKENS, 256>>>(xres, n2g, n2b, h2);

    {
        EpiFC1 e{fc1_b, fc1o};
        gemm_tf32_kernel<EpiFC1><<<dim3(HIDDEN / 128, T_TOKENS / 128), 256>>>(h2, fc1_w, CH, e);
    }
    {
        EpiFC2 e{fc2_b, xres, y};
        gemm_tf32_kernel<EpiFC2><<<dim3(CH / 128, T_TOKENS / 128), 256>>>(fc1o, fc2_w, HIDDEN, e);
    }

    transpose_out_kernel<<<tgrid, tb>>>(y, out);
}